// round 16
// baseline (speedup 1.0000x reference)
#include <cuda_runtime.h>
#include <cuda_fp16.h>
#include <cstdint>

// ---------------------------------------------------------------------------
// NittaConv2d: 3x3 conv, stride 1, pad 1, N=32 Cin=128 H=W=112 Cout=256, fp32.
// fp16 implicit GEMM on mma.sync.m16n8k16 (plain sm_103 PTX target).
// K reordered: k = r*128 + c  ->  fixed filter tap per BK=64 iteration.
// v4: image pre-converted to fp16 (padded); A producer loads pos-contiguous
// LDG.128 + shfl/byte_perm shift for the +-1 column taps + mask-zero edges;
// A smem k-major with XOR(mtile) swizzle; consumer uses ldmatrix.x4.trans.
// 512 threads, 16 warps of 64x32. B path: cp.async, 144B rows (unchanged).
// ---------------------------------------------------------------------------

#define CIN    128
#define COUT   256
#define HH     112
#define WW     112
#define HW     12544
#define KTOT   1152
#define NITER  18
#define BM     128
#define GRID   3136
#define THREADS 512
#define IMGTOT (32 * CIN * HW)        // 51,380,224 halves

// smem byte offsets
#define SM_BIAS  0                    // 1024 B
#define SM_A0    1024                 // 32 blocks * 512B = 16384 / buffer
#define SM_A1    (SM_A0 + 16384)
#define SM_B0    (SM_A1 + 16384)      // 256 rows * 144B = 36864 / buffer
#define SM_B1    (SM_B0 + 36864)
#define SM_TOTAL (SM_B1 + 36864)      // 107520

#define BROW     144

__device__ __half g_wh[COUT * KTOT];
__device__ __half g_imgh[IMGTOT + 256];     // +-128-half zero padding

static __device__ __forceinline__ uint32_t smem_u32(const void* p) {
    uint32_t a;
    asm("{ .reg .u64 t; cvta.to.shared.u64 t, %1; cvt.u32.u64 %0, t; }"
        : "=r"(a) : "l"(p));
    return a;
}

__global__ void convert_weights_kernel(const float* __restrict__ wgt) {
    int i = blockIdx.x * blockDim.x + threadIdx.x;
    if (i < COUT * KTOT) {
        const int co = i / KTOT;
        const int ko = i - co * KTOT;                // r*128 + c
        const int r  = ko >> 7;
        const int c  = ko & 127;
        g_wh[i] = __float2half(wgt[co * KTOT + c * 9 + r]);
    }
}

__global__ void convert_image_kernel(const float* __restrict__ img) {
    int i = blockIdx.x * blockDim.x + threadIdx.x;   // one float4 each
    if (i < IMGTOT / 4) {
        const float4 v = __ldg((const float4*)img + i);
        const __half2 a = __floats2half2_rn(v.x, v.y);
        const __half2 b = __floats2half2_rn(v.z, v.w);
        uint2 u;
        u.x = *(const uint32_t*)&a;
        u.y = *(const uint32_t*)&b;
        *((uint2*)(g_imgh + 128) + i) = u;
    }
}

// ---- A producer: 2 chunks (c0 and c0+32), each = 8 consecutive pos, 1 k-row.
//      LDG.128 aligned + shfl/byte_perm shift for fw!=1 + mask-zero edges. ----
static __device__ __forceinline__ void ldgA(int iter,
                                            const __half* __restrict__ sb,
                                            int c0, int pg, const uint32_t mB[3],
                                            uint32_t y[8]) {
    const int r  = iter >> 1;
    const int fh = r / 3, fw = r - fh * 3;
    const uint32_t mbyte = (mB[r >> 2] >> ((r & 3) * 8)) & 0xFFu;
    uint32_t mk[4];
    #pragma unroll
    for (int i = 0; i < 4; i++)
        mk[i] = (((mbyte >> (2 * i)) & 1u) ? 0x0000FFFFu : 0u)
              | (((mbyte >> (2 * i + 1)) & 1u) ? 0xFFFF0000u : 0u);

    const __half* s0 = sb + (size_t)((iter & 1) * 64 + c0) * HW + (fh - 1) * WW;
    #pragma unroll
    for (int ch = 0; ch < 2; ch++) {
        const __half* s = s0 + (size_t)(ch * 32) * HW;
        const uint4 M = *(const uint4*)s;
        uint32_t* yy = y + ch * 4;
        if (fw == 1) {
            yy[0] = M.x; yy[1] = M.y; yy[2] = M.z; yy[3] = M.w;
        } else if (fw == 0) {
            uint32_t prev = __shfl_up_sync(0xFFFFFFFFu, M.w, 1);
            if (pg == 0)
                prev = ((uint32_t)*(const unsigned short*)(s - 1)) << 16;
            yy[0] = __byte_perm(prev, M.x, 0x5432);
            yy[1] = __byte_perm(M.x, M.y, 0x5432);
            yy[2] = __byte_perm(M.y, M.z, 0x5432);
            yy[3] = __byte_perm(M.z, M.w, 0x5432);
        } else {
            uint32_t nxt = __shfl_down_sync(0xFFFFFFFFu, M.x, 1);
            if (pg == 15)
                nxt = (uint32_t)*(const unsigned short*)(s + 8);
            yy[0] = __byte_perm(M.x, M.y, 0x5432);
            yy[1] = __byte_perm(M.y, M.z, 0x5432);
            yy[2] = __byte_perm(M.z, M.w, 0x5432);
            yy[3] = __byte_perm(M.w, nxt, 0x5432);
        }
        yy[0] &= mk[0]; yy[1] &= mk[1]; yy[2] &= mk[2]; yy[3] &= mk[3];
    }
}

static __device__ __forceinline__ void stsA(char* abuf, int off0, const uint32_t y[8]) {
    *(uint4*)(abuf + off0)        = make_uint4(y[0], y[1], y[2], y[3]);
    *(uint4*)(abuf + off0 + 8192) = make_uint4(y[4], y[5], y[6], y[7]);
}

// ---- B producer: 4 x 16B cp.async (256 rows x 128B per iter) ----
static __device__ __forceinline__ void cpB(char* bbuf, int iter, int coB, int jb) {
    #pragma unroll
    for (int it = 0; it < 4; it++) {
        const int co = coB + 64 * it;
        const __half* src = g_wh + (size_t)co * KTOT + iter * 64 + jb * 8;
        const uint32_t dst = smem_u32(bbuf + co * BROW + jb * 16);
        asm volatile("cp.async.cg.shared.global [%0], [%1], 16;"
                     :: "r"(dst), "l"(src) : "memory");
    }
}

// ---- consumer: ldmatrix.x4.trans for A, LDS.32 pairs for B, 16 mmas/ks ----
static __device__ __forceinline__ void compute_half(uint32_t aS, const char* bbuf,
                                                    int mw, int nw, int lane, int ks0,
                                                    float acc[4][4][4]) {
    const int kp = (lane & 7) + ((lane >> 4) << 3);  // k' in 0..15
    const int ph = (lane >> 3) & 1;                  // pos half
    #pragma unroll
    for (int ks = ks0; ks < ks0 + 2; ks++) {
        uint32_t a[4][4];
        #pragma unroll
        for (int mi = 0; mi < 4; mi++) {
            const int mt = mw * 4 + mi;
            const uint32_t addr = aS + (ks * 8 + mt) * 512
                                + (((2 * kp + ph) ^ (mt << 2)) << 4);
            asm volatile(
                "ldmatrix.sync.aligned.m8n8.x4.trans.shared.b16 {%0,%1,%2,%3}, [%4];"
                : "=r"(a[mi][0]), "=r"(a[mi][1]), "=r"(a[mi][2]), "=r"(a[mi][3])
                : "r"(addr));
        }
        uint32_t b[4][2];
        #pragma unroll
        for (int ni = 0; ni < 4; ni++) {
            const int co = nw * 32 + ni * 8 + (lane >> 2);
            const char* p = bbuf + co * BROW + ks * 32 + (lane & 3) * 4;
            b[ni][0] = *(const uint32_t*)p;
            b[ni][1] = *(const uint32_t*)(p + 16);
        }
        #pragma unroll
        for (int mi = 0; mi < 4; mi++) {
            #pragma unroll
            for (int ni = 0; ni < 4; ni++) {
                asm volatile(
                    "mma.sync.aligned.m16n8k16.row.col.f32.f16.f16.f32 "
                    "{%0,%1,%2,%3}, {%4,%5,%6,%7}, {%8,%9}, {%0,%1,%2,%3};"
                    : "+f"(acc[mi][ni][0]), "+f"(acc[mi][ni][1]),
                      "+f"(acc[mi][ni][2]), "+f"(acc[mi][ni][3])
                    : "r"(a[mi][0]), "r"(a[mi][1]), "r"(a[mi][2]), "r"(a[mi][3]),
                      "r"(b[ni][0]), "r"(b[ni][1]));
            }
        }
    }
}

__global__ void __launch_bounds__(THREADS, 1)
nitta_conv_v4_kernel(float* __restrict__ out, const float* __restrict__ bias)
{
    extern __shared__ char smem[];
    const int tid  = threadIdx.x;
    const int wid  = tid >> 5;
    const int lane = tid & 31;

    float* biasS = (float*)(smem + SM_BIAS);
    if (tid < COUT) biasS[tid] = bias[tid];

    const int p0t = blockIdx.x * BM;
    const int n   = p0t / HW;
    const int hw0 = p0t - n * HW;

    // ---- A producer coords: warp w -> k-rows {2w, 2w+1} (+32), lane&15 = pg ----
    const int c0 = 2 * wid + (lane >> 4);
    const int pg = lane & 15;
    const int p0 = hw0 + pg * 8;
    const int h0 = p0 / WW;
    const int w0 = p0 - h0 * WW;
    const __half* __restrict__ sb = g_imgh + 128 + (size_t)n * (CIN * HW) + p0;

    // precompute 9 tap validity bytes (8 pos each)
    uint32_t mB[3] = {0, 0, 0};
    #pragma unroll
    for (int r = 0; r < 9; r++) {
        const int fh = r / 3, fw = r - fh * 3;
        uint32_t byte = 0;
        #pragma unroll
        for (int j = 0; j < 8; j++) {
            int w = w0 + j, h = h0;
            if (w >= WW) { w -= WW; h += 1; }
            const int ih = h + fh - 1, iw = w + fw - 1;
            if ((unsigned)ih < (unsigned)HH && (unsigned)iw < (unsigned)WW)
                byte |= 1u << j;
        }
        mB[r >> 2] |= byte << ((r & 3) * 8);
    }

    // A STS offset: block (s=c0>>4)*8 + mt, unit = (2k'+ph) ^ (mt<<2)
    const int mtP  = pg >> 1;
    const int off0 = ((c0 >> 4) * 8 + mtP) * 512
                   + (((2 * (c0 & 15) + (pg & 1)) ^ (mtP << 2)) << 4);

    // ---- B producer coords ----
    const int jb  = tid & 7;
    const int coB = tid >> 3;

    // ---- consumer coords: warp (mw, nw) owns 64x32 ----
    const int mw = wid >> 3;
    const int nw = wid & 7;
    const uint32_t sbase = smem_u32(smem);
    const uint32_t aS0 = sbase + SM_A0, aS1 = sbase + SM_A1;

    float acc[4][4][4];
    #pragma unroll
    for (int i = 0; i < 4; i++)
        #pragma unroll
        for (int j = 0; j < 4; j++)
            #pragma unroll
            for (int s = 0; s < 4; s++) acc[i][j][s] = 0.0f;

    // ---- prologue: fill buffer 0 with iter 0 ----
    uint32_t y[8];
    cpB(smem + SM_B0, 0, coB, jb);
    asm volatile("cp.async.commit_group;" ::: "memory");
    ldgA(0, sb, c0, pg, mB, y);
    stsA(smem + SM_A0, off0, y);
    asm volatile("cp.async.wait_group 0;" ::: "memory");
    __syncthreads();

    // ---- main loop ----
    for (int i = 0; i < NITER; i++) {
        const uint32_t aS = (i & 1) ? aS1 : aS0;
        char* bb  = (i & 1) ? (smem + SM_B1) : (smem + SM_B0);
        char* abN = (i & 1) ? (smem + SM_A0) : (smem + SM_A1);
        char* bbN = (i & 1) ? (smem + SM_B0) : (smem + SM_B1);
        const bool more = (i + 1 < NITER);

        if (more) {
            cpB(bbN, i + 1, coB, jb);
            asm volatile("cp.async.commit_group;" ::: "memory");
            ldgA(i + 1, sb, c0, pg, mB, y);
        }

        compute_half(aS, bb, mw, nw, lane, 0, acc);   // ks 0,1 hides LDG

        if (more) stsA(abN, off0, y);

        compute_half(aS, bb, mw, nw, lane, 2, acc);   // ks 2,3

        if (more) asm volatile("cp.async.wait_group 0;" ::: "memory");
        __syncthreads();
    }

    // ---- epilogue ----
    {
        const int rowb = mw * 64 + (lane >> 2);
        const int t2   = (lane & 3) * 2;
        float* __restrict__ outn = out + (size_t)n * ((size_t)COUT * HW) + hw0;
        #pragma unroll
        for (int mi = 0; mi < 4; mi++) {
            const int r0 = rowb + mi * 16;
            #pragma unroll
            for (int ni = 0; ni < 4; ni++) {
                const int co = nw * 32 + ni * 8 + t2;
                const float b0 = biasS[co];
                const float b1 = biasS[co + 1];
                outn[(size_t)co * HW + r0]           = acc[mi][ni][0] + b0;
                outn[(size_t)(co + 1) * HW + r0]     = acc[mi][ni][1] + b1;
                outn[(size_t)co * HW + r0 + 8]       = acc[mi][ni][2] + b0;
                outn[(size_t)(co + 1) * HW + r0 + 8] = acc[mi][ni][3] + b1;
            }
        }
    }
}

extern "C" void kernel_launch(void* const* d_in, const int* in_sizes, int n_in,
                              void* d_out, int out_size)
{
    const float* img  = (const float*)d_in[0];   // 32*128*112*112
    const float* wgt  = (const float*)d_in[1];   // 256*128*3*3
    const float* bias = (const float*)d_in[2];   // 256
    float* out = (float*)d_out;                  // 32*256*112*112

    convert_image_kernel<<<(IMGTOT / 4 + 255) / 256, 256>>>(img);
    convert_weights_kernel<<<(COUT * KTOT + 255) / 256, 256>>>(wgt);

    cudaFuncSetAttribute(nitta_conv_v4_kernel,
                         cudaFuncAttributeMaxDynamicSharedMemorySize, SM_TOTAL);
    nitta_conv_v4_kernel<<<GRID, THREADS, SM_TOTAL>>>(out, bias);
}

// round 17
// speedup vs baseline: 1.1808x; 1.1808x over previous
#include <cuda_runtime.h>
#include <cuda_fp16.h>
#include <cstdint>

// ---------------------------------------------------------------------------
// NittaConv2d: 3x3 conv, stride 1, pad 1, N=32 Cin=128 H=W=112 Cout=256, fp32.
// fp16 implicit GEMM on mma.sync.m16n8k16 (plain sm_103 PTX target).
// K reordered: k = r*128 + c  ->  fixed filter tap per BK=64 iteration.
// v5: v4's cheap A producer (image pre-converted fp16, pos-contiguous LDG.128,
// shfl/byte_perm column shift, mask-zero edges) + NEW conflict-free A layout:
//   k-major rows (64 x 256B), 16B chunk c of row k stored at c ^ (k&7).
//   STS.128 and ldmatrix.x4.trans both provably bank-conflict-free.
// 512 threads, 16 warps of 64x32. B path: cp.async, 144B rows (v3, proven).
// ---------------------------------------------------------------------------

#define CIN    128
#define COUT   256
#define HH     112
#define WW     112
#define HW     12544
#define KTOT   1152
#define NITER  18
#define BM     128
#define GRID   3136
#define THREADS 512
#define IMGTOT (32 * CIN * HW)

// smem byte offsets
#define SM_BIAS  0                    // 1024 B
#define SM_A0    1024                 // 64 rows * 256B = 16384 / buffer
#define SM_A1    (SM_A0 + 16384)
#define SM_B0    (SM_A1 + 16384)      // 256 rows * 144B = 36864 / buffer
#define SM_B1    (SM_B0 + 36864)
#define SM_TOTAL (SM_B1 + 36864)      // 107520

#define BROW     144

__device__ __half g_wh[COUT * KTOT];
__device__ __align__(16) __half g_imgh[IMGTOT + 256];   // +-128-half zero pad

static __device__ __forceinline__ uint32_t smem_u32(const void* p) {
    uint32_t a;
    asm("{ .reg .u64 t; cvta.to.shared.u64 t, %1; cvt.u32.u64 %0, t; }"
        : "=r"(a) : "l"(p));
    return a;
}

__global__ void convert_weights_kernel(const float* __restrict__ wgt) {
    int i = blockIdx.x * blockDim.x + threadIdx.x;
    if (i < COUT * KTOT) {
        const int co = i / KTOT;
        const int ko = i - co * KTOT;                // r*128 + c
        const int r  = ko >> 7;
        const int c  = ko & 127;
        g_wh[i] = __float2half(wgt[co * KTOT + c * 9 + r]);
    }
}

__global__ void convert_image_kernel(const float* __restrict__ img) {
    int i = blockIdx.x * blockDim.x + threadIdx.x;
    if (i < IMGTOT / 4) {
        const float4 v = __ldg((const float4*)img + i);
        const __half2 a = __floats2half2_rn(v.x, v.y);
        const __half2 b = __floats2half2_rn(v.z, v.w);
        uint2 u;
        u.x = *(const uint32_t*)&a;
        u.y = *(const uint32_t*)&b;
        *((uint2*)(g_imgh + 128) + i) = u;
    }
}

// ---- A producer (v4, proven correct): 2 chunks (k = c0, c0+32), each 8
//      consecutive pos. LDG.128 + shfl/byte_perm shift + mask-zero edges. ----
static __device__ __forceinline__ void ldgA(int iter,
                                            const __half* __restrict__ sb,
                                            int c0, int pg, const uint32_t mB[3],
                                            uint32_t y[8]) {
    const int r  = iter >> 1;
    const int fh = r / 3, fw = r - fh * 3;
    const uint32_t mbyte = (mB[r >> 2] >> ((r & 3) * 8)) & 0xFFu;
    uint32_t mk[4];
    #pragma unroll
    for (int i = 0; i < 4; i++)
        mk[i] = (((mbyte >> (2 * i)) & 1u) ? 0x0000FFFFu : 0u)
              | (((mbyte >> (2 * i + 1)) & 1u) ? 0xFFFF0000u : 0u);

    const __half* s0 = sb + (size_t)((iter & 1) * 64 + c0) * HW + (fh - 1) * WW;
    #pragma unroll
    for (int ch = 0; ch < 2; ch++) {
        const __half* s = s0 + (size_t)(ch * 32) * HW;
        const uint4 M = *(const uint4*)s;
        uint32_t* yy = y + ch * 4;
        if (fw == 1) {
            yy[0] = M.x; yy[1] = M.y; yy[2] = M.z; yy[3] = M.w;
        } else if (fw == 0) {
            uint32_t prev = __shfl_up_sync(0xFFFFFFFFu, M.w, 1);
            if (pg == 0)
                prev = ((uint32_t)*(const unsigned short*)(s - 1)) << 16;
            yy[0] = __byte_perm(prev, M.x, 0x5432);
            yy[1] = __byte_perm(M.x, M.y, 0x5432);
            yy[2] = __byte_perm(M.y, M.z, 0x5432);
            yy[3] = __byte_perm(M.z, M.w, 0x5432);
        } else {
            uint32_t nxt = __shfl_down_sync(0xFFFFFFFFu, M.x, 1);
            if (pg == 15)
                nxt = (uint32_t)*(const unsigned short*)(s + 8);
            yy[0] = __byte_perm(M.x, M.y, 0x5432);
            yy[1] = __byte_perm(M.y, M.z, 0x5432);
            yy[2] = __byte_perm(M.z, M.w, 0x5432);
            yy[3] = __byte_perm(M.w, nxt, 0x5432);
        }
        yy[0] &= mk[0]; yy[1] &= mk[1]; yy[2] &= mk[2]; yy[3] &= mk[3];
    }
}

// ---- A STS: row k = c0 (+32), chunk pg stored at pg ^ (c0&7). Conflict-free.
static __device__ __forceinline__ void stsA(char* abuf, int off0, const uint32_t y[8]) {
    *(uint4*)(abuf + off0)        = make_uint4(y[0], y[1], y[2], y[3]);
    *(uint4*)(abuf + off0 + 8192) = make_uint4(y[4], y[5], y[6], y[7]);
}

// ---- B producer: 4 x 16B cp.async (256 rows x 128B per iter) ----
static __device__ __forceinline__ void cpB(char* bbuf, int iter, int coB, int jb) {
    #pragma unroll
    for (int it = 0; it < 4; it++) {
        const int co = coB + 64 * it;
        const __half* src = g_wh + (size_t)co * KTOT + iter * 64 + jb * 8;
        const uint32_t dst = smem_u32(bbuf + co * BROW + jb * 16);
        asm volatile("cp.async.cg.shared.global [%0], [%1], 16;"
                     :: "r"(dst), "l"(src) : "memory");
    }
}

// ---- consumer: ldmatrix.x4.trans A (conflict-free), v3 B LDS, 16 mmas/ks ----
// lane l: matrix = l>>3; krow = ((l>>4)<<3)+(l&7); mcol8 = (l>>3)&1.
// addr = aS + ks*4096 + krow*256 + ((((mt<<1)|mcol8) ^ (l&7)) << 4)
static __device__ __forceinline__ void compute_half(uint32_t aS, const char* bbuf,
                                                    int mw, int nw, int lane, int ks0,
                                                    float acc[4][4][4]) {
    const uint32_t laneBase = aS + (((lane >> 4) << 3) + (lane & 7)) * 256;
    const int fragLo = (lane >> 3) & 1;      // mcol8
    const int lx     = lane & 7;
    #pragma unroll
    for (int ks = ks0; ks < ks0 + 2; ks++) {
        uint32_t a[4][4];
        #pragma unroll
        for (int mi = 0; mi < 4; mi++) {
            const int mt = mw * 4 + mi;
            const uint32_t addr = laneBase + ks * 4096
                                + ((((mt << 1) | fragLo) ^ lx) << 4);
            asm volatile(
                "ldmatrix.sync.aligned.m8n8.x4.trans.shared.b16 {%0,%1,%2,%3}, [%4];"
                : "=r"(a[mi][0]), "=r"(a[mi][1]), "=r"(a[mi][2]), "=r"(a[mi][3])
                : "r"(addr));
        }
        uint32_t b[4][2];
        #pragma unroll
        for (int ni = 0; ni < 4; ni++) {
            const int co = nw * 32 + ni * 8 + (lane >> 2);
            const char* p = bbuf + co * BROW + ks * 32 + (lane & 3) * 4;
            b[ni][0] = *(const uint32_t*)p;
            b[ni][1] = *(const uint32_t*)(p + 16);
        }
        #pragma unroll
        for (int mi = 0; mi < 4; mi++) {
            #pragma unroll
            for (int ni = 0; ni < 4; ni++) {
                asm volatile(
                    "mma.sync.aligned.m16n8k16.row.col.f32.f16.f16.f32 "
                    "{%0,%1,%2,%3}, {%4,%5,%6,%7}, {%8,%9}, {%0,%1,%2,%3};"
                    : "+f"(acc[mi][ni][0]), "+f"(acc[mi][ni][1]),
                      "+f"(acc[mi][ni][2]), "+f"(acc[mi][ni][3])
                    : "r"(a[mi][0]), "r"(a[mi][1]), "r"(a[mi][2]), "r"(a[mi][3]),
                      "r"(b[ni][0]), "r"(b[ni][1]));
            }
        }
    }
}

__global__ void __launch_bounds__(THREADS, 1)
nitta_conv_v5_kernel(float* __restrict__ out, const float* __restrict__ bias)
{
    extern __shared__ char smem[];
    const int tid  = threadIdx.x;
    const int wid  = tid >> 5;
    const int lane = tid & 31;

    float* biasS = (float*)(smem + SM_BIAS);
    if (tid < COUT) biasS[tid] = bias[tid];

    const int p0t = blockIdx.x * BM;
    const int n   = p0t / HW;
    const int hw0 = p0t - n * HW;

    // ---- A producer coords: warp w -> k-rows {2w, 2w+1} (+32), lane&15 = pg ----
    const int c0 = 2 * wid + (lane >> 4);
    const int pg = lane & 15;
    const int p0 = hw0 + pg * 8;
    const int h0 = p0 / WW;
    const int w0 = p0 - h0 * WW;
    const __half* __restrict__ sb = g_imgh + 128 + (size_t)n * (CIN * HW) + p0;

    // 9 tap-validity bytes (8 pos each)
    uint32_t mB[3] = {0, 0, 0};
    #pragma unroll
    for (int r = 0; r < 9; r++) {
        const int fh = r / 3, fw = r - fh * 3;
        uint32_t byte = 0;
        #pragma unroll
        for (int j = 0; j < 8; j++) {
            int w = w0 + j, h = h0;
            if (w >= WW) { w -= WW; h += 1; }
            const int ih = h + fh - 1, iw = w + fw - 1;
            if ((unsigned)ih < (unsigned)HH && (unsigned)iw < (unsigned)WW)
                byte |= 1u << j;
        }
        mB[r >> 2] |= byte << ((r & 3) * 8);
    }

    // A STS offset: row c0, chunk pg ^ (c0&7)  (low-3-bit XOR; bit 3 kept)
    const int chunkS = (pg & 8) | ((pg & 7) ^ (c0 & 7));
    const int off0   = c0 * 256 + chunkS * 16;

    // ---- B producer coords ----
    const int jb  = tid & 7;
    const int coB = tid >> 3;

    // ---- consumer coords: warp (mw, nw) owns 64x32 ----
    const int mw = wid >> 3;
    const int nw = wid & 7;
    const uint32_t sbase = smem_u32(smem);
    const uint32_t aS0 = sbase + SM_A0, aS1 = sbase + SM_A1;

    float acc[4][4][4];
    #pragma unroll
    for (int i = 0; i < 4; i++)
        #pragma unroll
        for (int j = 0; j < 4; j++)
            #pragma unroll
            for (int s = 0; s < 4; s++) acc[i][j][s] = 0.0f;

    // ---- prologue ----
    uint32_t y[8];
    cpB(smem + SM_B0, 0, coB, jb);
    asm volatile("cp.async.commit_group;" ::: "memory");
    ldgA(0, sb, c0, pg, mB, y);
    stsA(smem + SM_A0, off0, y);
    asm volatile("cp.async.wait_group 0;" ::: "memory");
    __syncthreads();

    // ---- main loop ----
    for (int i = 0; i < NITER; i++) {
        const uint32_t aS = (i & 1) ? aS1 : aS0;
        char* bb  = (i & 1) ? (smem + SM_B1) : (smem + SM_B0);
        char* abN = (i & 1) ? (smem + SM_A0) : (smem + SM_A1);
        char* bbN = (i & 1) ? (smem + SM_B0) : (smem + SM_B1);
        const bool more = (i + 1 < NITER);

        if (more) {
            cpB(bbN, i + 1, coB, jb);
            asm volatile("cp.async.commit_group;" ::: "memory");
            ldgA(i + 1, sb, c0, pg, mB, y);
        }

        compute_half(aS, bb, mw, nw, lane, 0, acc);   // ks 0,1 hides LDG

        if (more) stsA(abN, off0, y);

        compute_half(aS, bb, mw, nw, lane, 2, acc);   // ks 2,3

        if (more) asm volatile("cp.async.wait_group 0;" ::: "memory");
        __syncthreads();
    }

    // ---- epilogue ----
    {
        const int rowb = mw * 64 + (lane >> 2);
        const int t2   = (lane & 3) * 2;
        float* __restrict__ outn = out + (size_t)n * ((size_t)COUT * HW) + hw0;
        #pragma unroll
        for (int mi = 0; mi < 4; mi++) {
            const int r0 = rowb + mi * 16;
            #pragma unroll
            for (int ni = 0; ni < 4; ni++) {
                const int co = nw * 32 + ni * 8 + t2;
                const float b0 = biasS[co];
                const float b1 = biasS[co + 1];
                outn[(size_t)co * HW + r0]           = acc[mi][ni][0] + b0;
                outn[(size_t)(co + 1) * HW + r0]     = acc[mi][ni][1] + b1;
                outn[(size_t)co * HW + r0 + 8]       = acc[mi][ni][2] + b0;
                outn[(size_t)(co + 1) * HW + r0 + 8] = acc[mi][ni][3] + b1;
            }
        }
    }
}

extern "C" void kernel_launch(void* const* d_in, const int* in_sizes, int n_in,
                              void* d_out, int out_size)
{
    const float* img  = (const float*)d_in[0];   // 32*128*112*112
    const float* wgt  = (const float*)d_in[1];   // 256*128*3*3
    const float* bias = (const float*)d_in[2];   // 256
    float* out = (float*)d_out;                  // 32*256*112*112

    convert_image_kernel<<<(IMGTOT / 4 + 255) / 256, 256>>>(img);
    convert_weights_kernel<<<(COUT * KTOT + 255) / 256, 256>>>(wgt);

    cudaFuncSetAttribute(nitta_conv_v5_kernel,
                         cudaFuncAttributeMaxDynamicSharedMemorySize, SM_TOTAL);
    nitta_conv_v5_kernel<<<GRID, THREADS, SM_TOTAL>>>(out, bias);
}